// round 1
// baseline (speedup 1.0000x reference)
#include <cuda_runtime.h>
#include <cstdint>

#define T_DIM 4096
#define B_DIM 32
#define H_DIM 256
#define L_DIM 512
#define K_DIM 32
#define T_BLK 128

typedef unsigned long long ull;

// Scratch (allocation-free contract: __device__ globals)
__device__ __align__(16) float g_kern[B_DIM * H_DIM * K_DIM];   // packed pair layout
__device__ __align__(16) float g_glob[B_DIM * H_DIM];           // global_hidden (B,H)
__device__ __align__(16) float g_scores[T_DIM * B_DIM];         // scores (T,B)

// ---- Blackwell packed f32x2 helpers ----
__device__ __forceinline__ ull ffma2(ull a, ull b, ull c) {
    ull d; asm("fma.rn.f32x2 %0, %1, %2, %3;" : "=l"(d) : "l"(a), "l"(b), "l"(c)); return d;
}
__device__ __forceinline__ ull fadd2(ull a, ull b) {
    ull d; asm("add.rn.f32x2 %0, %1, %2;" : "=l"(d) : "l"(a), "l"(b)); return d;
}
__device__ __forceinline__ void unpack2(ull v, float& x, float& y) {
    asm("mov.b64 {%0, %1}, %2;" : "=f"(x), "=f"(y) : "l"(v));
}
__device__ __forceinline__ ull pack2(float x, float y) {
    ull v; asm("mov.b64 %0, {%1, %2};" : "=l"(v) : "f"(x), "f"(y)); return v;
}
__device__ __forceinline__ float tanh_ap(float x) {
    float y; asm("tanh.approx.f32 %0, %1;" : "=f"(y) : "f"(x)); return y;
}

// ============================================================================
// Kernel A: batched GEMV  out[b, row] = dot(lm[b,:], W[row,:]) + bias[row]
//   packed=1 -> write g_kern in (b, h/2, k, h&1) interleaved-pair layout
//   packed=0 -> write g_glob[b*nrows + row]
// blockDim (32, 8): x = b (one warp shares one W row -> broadcast loads)
// ============================================================================
__global__ void __launch_bounds__(256) gemv_kernel(
    const float* __restrict__ W, const float* __restrict__ bias,
    const float* __restrict__ lm, int nrows, int packed)
{
    int b   = threadIdx.x;                       // 0..31
    int row = blockIdx.x * 8 + threadIdx.y;      // output row
    if (row >= nrows) return;

    const ulonglong2* w2 = reinterpret_cast<const ulonglong2*>(W + (size_t)row * L_DIM);
    const ulonglong2* a2 = reinterpret_cast<const ulonglong2*>(lm + (size_t)b * L_DIM);

    ull acc0 = 0, acc1 = 0;
    #pragma unroll 8
    for (int i = 0; i < L_DIM / 4; i++) {        // 128 iters of 4 floats
        ulonglong2 wv = w2[i];
        ulonglong2 av = a2[i];
        acc0 = ffma2(av.x, wv.x, acc0);
        acc1 = ffma2(av.y, wv.y, acc1);
    }
    float x0, y0, x1, y1;
    unpack2(acc0, x0, y0);
    unpack2(acc1, x1, y1);
    float s = (x0 + x1) + (y0 + y1) + bias[row];

    if (packed) {
        int h = row >> 5;          // row = h*K + k
        int k = row & 31;
        g_kern[(size_t)b * (H_DIM * K_DIM) + ((h >> 1) << 6) + (k << 1) + (h & 1)] = s;
    } else {
        g_glob[(size_t)b * nrows + row] = s;
    }
}

// ============================================================================
// Kernel B: fused conv + global + tanh + Ws reduction -> scores (T,B)
// Grid: (T/T_BLK, B). Block: 128 threads (4 warps). Each lane owns the
// h-pair (2*tid, 2*tid+1); conv taps packed in 32 u64 registers; prev window
// slides through an 8-deep rotating register buffer (1 LDS.64 per k per 8 t).
// ============================================================================
__global__ void __launch_bounds__(128) score_kernel(
    const float* __restrict__ enc,   // (T,B,H)
    const float* __restrict__ prev,  // (T,B)
    const float* __restrict__ Ws,    // (H)
    const float* __restrict__ bsp)   // (1)
{
    const int b   = blockIdx.y;
    const int t0  = blockIdx.x * T_BLK;
    const int tid = threadIdx.x;
    const int warp = tid >> 5;
    const int lane = tid & 31;

    __shared__ ull  wdup[T_BLK + 40];     // duplicated-pair prev_pad window
    __shared__ float part[T_BLK][4];      // per-warp partial score sums

    // Fill prev_pad window: wdup[i] = prev_pad[t0+i] = prev[t0+i-31] (0 if OOB)
    for (int i = tid; i < T_BLK + 40; i += 128) {
        int tg = t0 + i - (K_DIM - 1);
        float v = (tg >= 0 && tg < T_DIM) ? prev[(size_t)tg * B_DIM + b] : 0.f;
        wdup[i] = pack2(v, v);
    }

    // Load packed conv taps: 32 u64 (kern[b,h0,k] | kern[b,h1,k])
    ull kern2[32];
    {
        const ulonglong2* kp = reinterpret_cast<const ulonglong2*>(g_kern)
                             + (size_t)b * 2048 + (size_t)tid * 16;
        #pragma unroll
        for (int i = 0; i < 16; i++) {
            ulonglong2 v = kp[i];
            kern2[2 * i]     = v.x;
            kern2[2 * i + 1] = v.y;
        }
    }
    const ull   gv   = *reinterpret_cast<const ull*>(g_glob + (size_t)b * H_DIM + 2 * tid);
    const float2 wsv = *reinterpret_cast<const float2*>(Ws + 2 * tid);
    const float bs_val = bsp[0];

    __syncthreads();

    const float* encbase = enc + ((size_t)t0 * B_DIM + b) * H_DIM + 2 * tid;

    #pragma unroll 1
    for (int j0 = 0; j0 < T_BLK; j0 += 8) {
        // rolling 8-deep window
        ull w[8];
        #pragma unroll
        for (int i = 0; i < 8; i++) w[i] = wdup[j0 + i];
        ull acc[8];
        #pragma unroll
        for (int i = 0; i < 8; i++) acc[i] = 0ull;

        #pragma unroll
        for (int k = 0; k < K_DIM; k++) {
            ull kk = kern2[k];
            #pragma unroll
            for (int tt = 0; tt < 8; tt++)
                acc[tt] = ffma2(kk, w[(k + tt) & 7], acc[tt]);
            w[k & 7] = wdup[j0 + k + 8];
        }

        // epilogue: enc + local + global -> tanh -> Ws dot -> warp reduce
        #pragma unroll
        for (int tt = 0; tt < 8; tt++) {
            ull e2 = *reinterpret_cast<const ull*>(
                encbase + (size_t)(j0 + tt) * (B_DIM * H_DIM));
            ull h2 = fadd2(fadd2(e2, acc[tt]), gv);
            float hx, hy;
            unpack2(h2, hx, hy);
            float v = fmaf(wsv.y, tanh_ap(hy), wsv.x * tanh_ap(hx));
            v += __shfl_xor_sync(0xFFFFFFFFu, v, 16);
            v += __shfl_xor_sync(0xFFFFFFFFu, v, 8);
            v += __shfl_xor_sync(0xFFFFFFFFu, v, 4);
            v += __shfl_xor_sync(0xFFFFFFFFu, v, 2);
            v += __shfl_xor_sync(0xFFFFFFFFu, v, 1);
            if (lane == 0) part[j0 + tt][warp] = v;
        }
    }
    __syncthreads();

    // 128 threads finalize one t each
    float s = part[tid][0] + part[tid][1] + part[tid][2] + part[tid][3] + bs_val;
    g_scores[(size_t)(t0 + tid) * B_DIM + b] = s;
}

// ============================================================================
// Kernel C: softmax over T per column b (scores + mask), write out (T,B)
// ============================================================================
__global__ void __launch_bounds__(256) softmax_kernel(
    const float* __restrict__ mask, float* __restrict__ out)
{
    __shared__ float sc[T_DIM];
    __shared__ float red[256];
    const int b = blockIdx.x;
    const int tid = threadIdx.x;

    float m = -1e30f;
    for (int t = tid; t < T_DIM; t += 256) {
        float s = g_scores[(size_t)t * B_DIM + b] + mask[(size_t)t * B_DIM + b];
        sc[t] = s;
        m = fmaxf(m, s);
    }
    red[tid] = m;
    __syncthreads();
    for (int o = 128; o > 0; o >>= 1) {
        if (tid < o) red[tid] = fmaxf(red[tid], red[tid + o]);
        __syncthreads();
    }
    m = red[0];
    __syncthreads();

    float sum = 0.f;
    for (int t = tid; t < T_DIM; t += 256) {
        float e = __expf(sc[t] - m);
        sc[t] = e;
        sum += e;
    }
    red[tid] = sum;
    __syncthreads();
    for (int o = 128; o > 0; o >>= 1) {
        if (tid < o) red[tid] += red[tid + o];
        __syncthreads();
    }
    float inv = 1.0f / red[0];

    for (int t = tid; t < T_DIM; t += 256)
        out[(size_t)t * B_DIM + b] = sc[t] * inv;
}

// ============================================================================
extern "C" void kernel_launch(void* const* d_in, const int* in_sizes, int n_in,
                              void* d_out, int out_size)
{
    const float* enc  = (const float*)d_in[0];
    const float* mask = (const float*)d_in[1];
    const float* lm   = (const float*)d_in[2];
    const float* prev = (const float*)d_in[3];
    const float* Wk   = (const float*)d_in[4];
    const float* bk   = (const float*)d_in[5];
    const float* Wg   = (const float*)d_in[6];
    const float* bg   = (const float*)d_in[7];
    const float* Ws   = (const float*)d_in[8];
    const float* bs   = (const float*)d_in[9];
    float* out = (float*)d_out;

    // dynamic conv kernels (B,H,K) in packed-pair layout
    gemv_kernel<<<dim3((K_DIM * H_DIM) / 8), dim3(32, 8)>>>(Wk, bk, lm, K_DIM * H_DIM, 1);
    // global hidden (B,H)
    gemv_kernel<<<dim3(H_DIM / 8), dim3(32, 8)>>>(Wg, bg, lm, H_DIM, 0);
    // fused conv + tanh + score
    score_kernel<<<dim3(T_DIM / T_BLK, B_DIM), 128>>>(enc, prev, Ws, bs);
    // softmax over time
    softmax_kernel<<<B_DIM, 256>>>(mask, out);
}

// round 2
// speedup vs baseline: 2.4164x; 2.4164x over previous
#include <cuda_runtime.h>
#include <cstdint>

#define T_DIM 4096
#define B_DIM 32
#define H_DIM 256
#define L_DIM 512
#define K_DIM 32
#define T_BLK 128
#define GR    64        // rows per gemm block

typedef unsigned long long ull;

// Scratch (allocation-free contract: __device__ globals)
__device__ __align__(16) float g_kern[B_DIM * H_DIM * K_DIM];   // packed pair layout
__device__ __align__(16) float g_glob[B_DIM * H_DIM];           // global_hidden (B,H)
__device__ __align__(16) float g_exp[T_DIM * B_DIM];            // exp(score+mask)
__device__ __align__(16) float g_part[(T_DIM / T_BLK) * B_DIM]; // partial exp sums

// ---- Blackwell packed f32x2 helpers ----
__device__ __forceinline__ ull ffma2(ull a, ull b, ull c) {
    ull d; asm("fma.rn.f32x2 %0, %1, %2, %3;" : "=l"(d) : "l"(a), "l"(b), "l"(c)); return d;
}
__device__ __forceinline__ ull fadd2(ull a, ull b) {
    ull d; asm("add.rn.f32x2 %0, %1, %2;" : "=l"(d) : "l"(a), "l"(b)); return d;
}
__device__ __forceinline__ void unpack2(ull v, float& x, float& y) {
    asm("mov.b64 {%0, %1}, %2;" : "=f"(x), "=f"(y) : "l"(v));
}
__device__ __forceinline__ ull pack2(float x, float y) {
    ull v; asm("mov.b64 %0, {%1, %2};" : "=l"(v) : "f"(x), "f"(y)); return v;
}
__device__ __forceinline__ float tanh_ap(float x) {
    float y; asm("tanh.approx.f32 %0, %1;" : "=f"(y) : "f"(x)); return y;
}

// ============================================================================
// Kernel A: tiled SGEMM  out[b, row] = dot(lm[b,:], W[row,:]) + bias[row]
// Block = GR rows x 32 b. blockIdx.x < 128 -> Wk rows (packed store into
// g_kern), else -> Wg rows (store g_glob). Both operands staged in smem with
// coalesced global loads; thread computes 8 rows x 1 b.
// ============================================================================
__global__ void __launch_bounds__(256) gemm_kernel(
    const float* __restrict__ Wk, const float* __restrict__ bk,
    const float* __restrict__ Wg, const float* __restrict__ bg,
    const float* __restrict__ lm)
{
    const int tid = threadIdx.x;
    const int tx = tid & 31;          // b
    const int ty = tid >> 5;          // row group 0..7

    const bool is_k = (blockIdx.x < (K_DIM * H_DIM) / GR);   // first 128 blocks
    const float* W    = is_k ? Wk : Wg;
    const float* bias = is_k ? bk : bg;
    const int rowbase = (is_k ? blockIdx.x : (blockIdx.x - (K_DIM * H_DIM) / GR)) * GR;

    __shared__ float4 Ws4[GR][16];        // 64 rows x 64 L-cols (as float4)
    __shared__ float  lm_s[GR][33];       // [l][b], padded

    float acc[8];
    #pragma unroll
    for (int j = 0; j < 8; j++) acc[j] = 0.f;

    for (int kk = 0; kk < L_DIM; kk += GR) {
        // W tile: 1024 float4 slots
        #pragma unroll
        for (int i = 0; i < 4; i++) {
            int s = tid + 256 * i;
            int row = s >> 4, c4 = s & 15;
            Ws4[row][c4] = *reinterpret_cast<const float4*>(
                W + (size_t)(rowbase + row) * L_DIM + kk + c4 * 4);
        }
        // lm tile: 64 l x 32 b (coalesced over l)
        #pragma unroll
        for (int i = 0; i < 8; i++) {
            int s = tid + 256 * i;
            int b = s >> 6, l = s & 63;
            lm_s[l][b] = lm[(size_t)b * L_DIM + kk + l];
        }
        __syncthreads();

        #pragma unroll
        for (int l4 = 0; l4 < 16; l4++) {
            float a0 = lm_s[4 * l4 + 0][tx];
            float a1 = lm_s[4 * l4 + 1][tx];
            float a2 = lm_s[4 * l4 + 2][tx];
            float a3 = lm_s[4 * l4 + 3][tx];
            #pragma unroll
            for (int j = 0; j < 8; j++) {
                float4 w = Ws4[ty * 8 + j][l4];
                acc[j] = fmaf(w.x, a0, acc[j]);
                acc[j] = fmaf(w.y, a1, acc[j]);
                acc[j] = fmaf(w.z, a2, acc[j]);
                acc[j] = fmaf(w.w, a3, acc[j]);
            }
        }
        __syncthreads();
    }

    #pragma unroll
    for (int j = 0; j < 8; j++) {
        int row = rowbase + ty * 8 + j;
        float s = acc[j] + bias[row];
        if (is_k) {
            int h = row >> 5;          // row = h*K + k
            int k = row & 31;
            g_kern[(size_t)tx * (H_DIM * K_DIM) + ((h >> 1) << 6) + (k << 1) + (h & 1)] = s;
        } else {
            g_glob[(size_t)tx * H_DIM + row] = s;
        }
    }
}

// ============================================================================
// Kernel B: fused conv + global + tanh + Ws reduce + exp -> g_exp, g_part
// Grid: (T/T_BLK, B). Block 128 threads. Lane owns h-pair (2t, 2t+1); conv
// taps packed in 32 u64 regs; prev window slides through 8-deep reg buffer.
// ============================================================================
__global__ void __launch_bounds__(128) score_kernel(
    const float* __restrict__ enc,   // (T,B,H)
    const float* __restrict__ prev,  // (T,B)
    const float* __restrict__ mask,  // (T,B)
    const float* __restrict__ Ws,    // (H)
    const float* __restrict__ bsp)   // (1)
{
    const int b   = blockIdx.y;
    const int t0  = blockIdx.x * T_BLK;
    const int tid = threadIdx.x;
    const int warp = tid >> 5;
    const int lane = tid & 31;

    __shared__ ull  wdup[T_BLK + 40];     // duplicated-pair prev_pad window
    __shared__ float part[T_BLK][4];      // per-warp partial score sums
    __shared__ float red4[4];

    for (int i = tid; i < T_BLK + 40; i += 128) {
        int tg = t0 + i - (K_DIM - 1);
        float v = (tg >= 0 && tg < T_DIM) ? prev[(size_t)tg * B_DIM + b] : 0.f;
        wdup[i] = pack2(v, v);
    }

    ull kern2[32];
    {
        const ulonglong2* kp = reinterpret_cast<const ulonglong2*>(g_kern)
                             + (size_t)b * 2048 + (size_t)tid * 16;
        #pragma unroll
        for (int i = 0; i < 16; i++) {
            ulonglong2 v = kp[i];
            kern2[2 * i]     = v.x;
            kern2[2 * i + 1] = v.y;
        }
    }
    const ull   gv   = *reinterpret_cast<const ull*>(g_glob + (size_t)b * H_DIM + 2 * tid);
    const float2 wsv = *reinterpret_cast<const float2*>(Ws + 2 * tid);
    const float bs_val = bsp[0];

    __syncthreads();

    const float* encbase = enc + ((size_t)t0 * B_DIM + b) * H_DIM + 2 * tid;

    #pragma unroll 1
    for (int j0 = 0; j0 < T_BLK; j0 += 8) {
        ull w[8];
        #pragma unroll
        for (int i = 0; i < 8; i++) w[i] = wdup[j0 + i];
        ull acc[8];
        #pragma unroll
        for (int i = 0; i < 8; i++) acc[i] = 0ull;

        #pragma unroll
        for (int k = 0; k < K_DIM; k++) {
            ull kk = kern2[k];
            #pragma unroll
            for (int tt = 0; tt < 8; tt++)
                acc[tt] = ffma2(kk, w[(k + tt) & 7], acc[tt]);
            w[k & 7] = wdup[j0 + k + 8];
        }

        #pragma unroll
        for (int tt = 0; tt < 8; tt++) {
            ull e2 = *reinterpret_cast<const ull*>(
                encbase + (size_t)(j0 + tt) * (B_DIM * H_DIM));
            ull h2 = fadd2(fadd2(e2, acc[tt]), gv);
            float hx, hy;
            unpack2(h2, hx, hy);
            float v = fmaf(wsv.y, tanh_ap(hy), wsv.x * tanh_ap(hx));
            v += __shfl_xor_sync(0xFFFFFFFFu, v, 16);
            v += __shfl_xor_sync(0xFFFFFFFFu, v, 8);
            v += __shfl_xor_sync(0xFFFFFFFFu, v, 4);
            v += __shfl_xor_sync(0xFFFFFFFFu, v, 2);
            v += __shfl_xor_sync(0xFFFFFFFFu, v, 1);
            if (lane == 0) part[j0 + tt][warp] = v;
        }
    }
    __syncthreads();

    // each thread finalizes one t: score -> +mask -> exp; block-reduce sum
    int t = t0 + tid;
    float s = part[tid][0] + part[tid][1] + part[tid][2] + part[tid][3] + bs_val;
    float e = __expf(s + mask[(size_t)t * B_DIM + b]);
    g_exp[(size_t)t * B_DIM + b] = e;

    float v = e;
    v += __shfl_xor_sync(0xFFFFFFFFu, v, 16);
    v += __shfl_xor_sync(0xFFFFFFFFu, v, 8);
    v += __shfl_xor_sync(0xFFFFFFFFu, v, 4);
    v += __shfl_xor_sync(0xFFFFFFFFu, v, 2);
    v += __shfl_xor_sync(0xFFFFFFFFu, v, 1);
    if (lane == 0) red4[warp] = v;
    __syncthreads();
    if (tid == 0)
        g_part[(size_t)blockIdx.x * B_DIM + b] = red4[0] + red4[1] + red4[2] + red4[3];
}

// ============================================================================
// Kernel C: normalize  out[t,b] = g_exp[t,b] / sum_b
// ============================================================================
__global__ void __launch_bounds__(128) norm_kernel(float* __restrict__ out)
{
    __shared__ float inv_s;
    const int b = blockIdx.y;
    const int tid = threadIdx.x;

    if (tid < 32) {
        float v = g_part[(size_t)tid * B_DIM + b];
        v += __shfl_xor_sync(0xFFFFFFFFu, v, 16);
        v += __shfl_xor_sync(0xFFFFFFFFu, v, 8);
        v += __shfl_xor_sync(0xFFFFFFFFu, v, 4);
        v += __shfl_xor_sync(0xFFFFFFFFu, v, 2);
        v += __shfl_xor_sync(0xFFFFFFFFu, v, 1);
        if (tid == 0) inv_s = 1.0f / v;
    }
    __syncthreads();

    int t = blockIdx.x * 128 + tid;
    out[(size_t)t * B_DIM + b] = g_exp[(size_t)t * B_DIM + b] * inv_s;
}

// ============================================================================
extern "C" void kernel_launch(void* const* d_in, const int* in_sizes, int n_in,
                              void* d_out, int out_size)
{
    const float* enc  = (const float*)d_in[0];
    const float* mask = (const float*)d_in[1];
    const float* lm   = (const float*)d_in[2];
    const float* prev = (const float*)d_in[3];
    const float* Wk   = (const float*)d_in[4];
    const float* bk   = (const float*)d_in[5];
    const float* Wg   = (const float*)d_in[6];
    const float* bg   = (const float*)d_in[7];
    const float* Ws   = (const float*)d_in[8];
    const float* bs   = (const float*)d_in[9];
    float* out = (float*)d_out;

    // Wk (128 blocks) + Wg (4 blocks) fused GEMM
    gemm_kernel<<<(K_DIM * H_DIM) / GR + H_DIM / GR, 256>>>(Wk, bk, Wg, bg, lm);
    // fused conv + tanh + score + exp + partial sums
    score_kernel<<<dim3(T_DIM / T_BLK, B_DIM), 128>>>(enc, prev, mask, Ws, bs);
    // normalize
    norm_kernel<<<dim3(T_DIM / 128, B_DIM), 128>>>(out);
}

// round 3
// speedup vs baseline: 3.5623x; 1.4743x over previous
#include <cuda_runtime.h>
#include <cstdint>

#define T_DIM 4096
#define B_DIM 32
#define H_DIM 256
#define L_DIM 512
#define K_DIM 32
#define T_BLK 128

// Scratch (allocation-free contract: __device__ globals)
__device__ __align__(16) float g_kern[B_DIM * H_DIM * K_DIM];   // [b][h][k] fp32
__device__ __align__(16) float g_glob[B_DIM * H_DIM];           // (B,H)
__device__ __align__(16) float g_exp[T_DIM * B_DIM];            // exp(score+mask)
__device__ __align__(16) float g_part[(T_DIM / T_BLK) * B_DIM]; // partial exp sums

// ---- helpers ----
__device__ __forceinline__ float tanh_ap(float x) {
    float y; asm("tanh.approx.f32 %0, %1;" : "=f"(y) : "f"(x)); return y;
}
__device__ __forceinline__ unsigned cvt_bf2(float lo, float hi) {
    unsigned d; asm("cvt.rn.bf16x2.f32 %0, %1, %2;" : "=r"(d) : "f"(hi), "f"(lo)); return d;
}
__device__ __forceinline__ uint32_t smem_u32(const void* p) {
    return (uint32_t)__cvta_generic_to_shared(p);
}
__device__ __forceinline__ void ldsm_x4(unsigned r[4], uint32_t addr) {
    asm volatile("ldmatrix.sync.aligned.m8n8.x4.shared.b16 {%0,%1,%2,%3}, [%4];"
        : "=r"(r[0]), "=r"(r[1]), "=r"(r[2]), "=r"(r[3]) : "r"(addr));
}
__device__ __forceinline__ void ldsm_x2(unsigned& r0, unsigned& r1, uint32_t addr) {
    asm volatile("ldmatrix.sync.aligned.m8n8.x2.shared.b16 {%0,%1}, [%2];"
        : "=r"(r0), "=r"(r1) : "r"(addr));
}
__device__ __forceinline__ void mma_bf16(float c[4], const unsigned a[4], const unsigned b[2]) {
    asm volatile("mma.sync.aligned.m16n8k16.row.col.f32.bf16.bf16.f32 "
        "{%0,%1,%2,%3}, {%4,%5,%6,%7}, {%8,%9}, {%0,%1,%2,%3};"
        : "+f"(c[0]), "+f"(c[1]), "+f"(c[2]), "+f"(c[3])
        : "r"(a[0]), "r"(a[1]), "r"(a[2]), "r"(a[3]), "r"(b[0]), "r"(b[1]));
}

// ============================================================================
// Kernel A: SGEMM  out[b, row] = dot(lm[b,:], W[row,:]) + bias[row]
// Block tile 32 rows x 32 b, 128 threads, thread tile 2 rows x 4 b.
// All smem reads float4 -> 6 LDS.128 per 32 FFMA per thread (fma-bound).
// ============================================================================
#define G_ROWS 32
#define G_LC   64
#define G_WP   68   // W tile pitch (floats), %4==0, 2-row stride 136%32=8 banks
#define G_LP   36   // lm tile pitch

__global__ void __launch_bounds__(128) gemm_kernel(
    const float* __restrict__ Wk, const float* __restrict__ bk,
    const float* __restrict__ Wg, const float* __restrict__ bg,
    const float* __restrict__ lm)
{
    const int tid = threadIdx.x;
    const int ty  = tid >> 3;          // row group 0..15 (2 rows each)
    const int txb = (tid & 7) * 4;     // b base (4 b each)

    const bool is_k = (blockIdx.x < (K_DIM * H_DIM) / G_ROWS);   // first 256 blocks
    const float* W    = is_k ? Wk : Wg;
    const float* bias = is_k ? bk : bg;
    const int rowbase = (is_k ? blockIdx.x : (blockIdx.x - (K_DIM * H_DIM) / G_ROWS)) * G_ROWS;

    __shared__ __align__(16) float Wt[G_ROWS * G_WP];
    __shared__ __align__(16) float lmt[G_LC * G_LP];

    float acc[2][4];
    #pragma unroll
    for (int r = 0; r < 2; r++)
        #pragma unroll
        for (int j = 0; j < 4; j++) acc[r][j] = 0.f;

    for (int kk = 0; kk < L_DIM; kk += G_LC) {
        // W tile: 32 rows x 64 cols = 512 float4 slots
        #pragma unroll
        for (int i = 0; i < 4; i++) {
            int s = tid + 128 * i;             // float4 slot
            int row = s >> 4, c4 = (s & 15) * 4;
            *reinterpret_cast<float4*>(&Wt[row * G_WP + c4]) =
                *reinterpret_cast<const float4*>(W + (size_t)(rowbase + row) * L_DIM + kk + c4);
        }
        // lm tile: 64 l x 32 b, coalesced over l
        #pragma unroll
        for (int i = 0; i < 16; i++) {
            int s = tid + 128 * i;
            int bb = s >> 6, l = s & 63;
            lmt[l * G_LP + bb] = lm[(size_t)bb * L_DIM + kk + l];
        }
        __syncthreads();

        #pragma unroll
        for (int l4 = 0; l4 < G_LC / 4; l4++) {
            float4 w0 = *reinterpret_cast<const float4*>(&Wt[(ty * 2 + 0) * G_WP + l4 * 4]);
            float4 w1 = *reinterpret_cast<const float4*>(&Wt[(ty * 2 + 1) * G_WP + l4 * 4]);
            float wr0[4] = {w0.x, w0.y, w0.z, w0.w};
            float wr1[4] = {w1.x, w1.y, w1.z, w1.w};
            #pragma unroll
            for (int i = 0; i < 4; i++) {
                float4 a = *reinterpret_cast<const float4*>(&lmt[(l4 * 4 + i) * G_LP + txb]);
                acc[0][0] = fmaf(wr0[i], a.x, acc[0][0]);
                acc[0][1] = fmaf(wr0[i], a.y, acc[0][1]);
                acc[0][2] = fmaf(wr0[i], a.z, acc[0][2]);
                acc[0][3] = fmaf(wr0[i], a.w, acc[0][3]);
                acc[1][0] = fmaf(wr1[i], a.x, acc[1][0]);
                acc[1][1] = fmaf(wr1[i], a.y, acc[1][1]);
                acc[1][2] = fmaf(wr1[i], a.z, acc[1][2]);
                acc[1][3] = fmaf(wr1[i], a.w, acc[1][3]);
            }
        }
        __syncthreads();
    }

    #pragma unroll
    for (int r = 0; r < 2; r++) {
        int row = rowbase + ty * 2 + r;
        float bv = bias[row];
        #pragma unroll
        for (int j = 0; j < 4; j++) {
            int bb = txb + j;
            float s = acc[r][j] + bv;
            if (is_k) g_kern[(size_t)bb * (H_DIM * K_DIM) + row] = s;   // row = h*K + k
            else      g_glob[(size_t)bb * H_DIM + row] = s;
        }
    }
}

// ============================================================================
// Kernel B: tensor-core conv + enc + global -> tanh -> Ws -> exp
// Block: (t-block of 128, b). 128 threads = 4 warps; warp owns 64 h.
// A (128x32 Hankel of prev_pad) and B (kern 256x32, n-major) staged bf16 in
// smem; mma.m16n8k16 accumulates fp32; epilogue maps C fragments onto enc.
// ============================================================================
__global__ void __launch_bounds__(128) score_kernel(
    const float* __restrict__ enc,   // (T,B,H)
    const float* __restrict__ prev,  // (T,B)
    const float* __restrict__ mask,  // (T,B)
    const float* __restrict__ Ws,    // (H)
    const float* __restrict__ bsp)   // (1)
{
    const int b    = blockIdx.y;
    const int t0   = blockIdx.x * T_BLK;
    const int tid  = threadIdx.x;
    const int wid  = tid >> 5;
    const int lane = tid & 31;
    const int gid  = lane >> 2;   // 0..7
    const int tig  = lane & 3;    // 0..3

    __shared__ float win_s[160];                       // prev_pad window
    __shared__ __align__(16) unsigned A_sm[128 * 20];  // bf16x2, pitch 20 u32 (40 halves)
    __shared__ __align__(16) unsigned B_sm[256 * 20];
    __shared__ float part[T_BLK][4];
    __shared__ float red4[4];

    // ---- fill prev window + B (kern -> bf16) ----
    for (int i = tid; i < 160; i += 128) {
        int tg = t0 + i - (K_DIM - 1);
        win_s[i] = (tg >= 0 && tg < T_DIM) ? prev[(size_t)tg * B_DIM + b] : 0.f;
    }
    {
        const float2* kp = reinterpret_cast<const float2*>(g_kern + (size_t)b * H_DIM * K_DIM);
        #pragma unroll
        for (int i = tid; i < (H_DIM * K_DIM) / 2; i += 128) {
            float2 v = kp[i];
            int h = i >> 4, k2 = i & 15;
            B_sm[h * 20 + k2] = cvt_bf2(v.x, v.y);
        }
    }
    __syncthreads();

    // ---- fill A (Hankel windows, bf16) ----
    {
        int r = tid;
        #pragma unroll
        for (int k2 = 0; k2 < 16; k2++)
            A_sm[r * 20 + k2] = cvt_bf2(win_s[r + 2 * k2], win_s[r + 2 * k2 + 1]);
    }

    // ---- B fragments (resident) + per-lane epilogue constants ----
    const int hw0 = wid * 64;
    unsigned Bf[8][2][2];
    {
        uint32_t bbase = smem_u32(B_sm);
        #pragma unroll
        for (int j = 0; j < 8; j++)
            #pragma unroll
            for (int kt = 0; kt < 2; kt++) {
                uint32_t addr = bbase + (uint32_t)(hw0 + j * 8 + (lane & 7)) * 80
                              + kt * 32 + ((lane >> 3) & 1) * 16;
                ldsm_x2(Bf[j][kt][0], Bf[j][kt][1], addr);
            }
    }
    float2 gv2[8], ws2[8];
    #pragma unroll
    for (int j = 0; j < 8; j++) {
        int h0 = hw0 + j * 8 + 2 * tig;
        gv2[j] = *reinterpret_cast<const float2*>(g_glob + (size_t)b * H_DIM + h0);
        ws2[j] = *reinterpret_cast<const float2*>(Ws + h0);
    }
    __syncthreads();

    const uint32_t abase = smem_u32(A_sm);
    const uint32_t a_off = (uint32_t)(lane & 15) * 80 + (uint32_t)(lane >> 4) * 16;

    #pragma unroll 1
    for (int m = 0; m < 8; m++) {
        unsigned a0[4], a1[4];
        ldsm_x4(a0, abase + (uint32_t)m * 16 * 80 + a_off);        // k 0..15
        ldsm_x4(a1, abase + (uint32_t)m * 16 * 80 + a_off + 32);   // k 16..31

        const int ta = t0 + m * 16 + gid;
        const float* e_row0 = enc + ((size_t)ta * B_DIM + b) * H_DIM;
        const float* e_row1 = e_row0 + (size_t)8 * B_DIM * H_DIM;

        float sum0 = 0.f, sum1 = 0.f;
        #pragma unroll
        for (int jh = 0; jh < 2; jh++) {
            float c[4][4];
            #pragma unroll
            for (int j4 = 0; j4 < 4; j4++) {
                c[j4][0] = c[j4][1] = c[j4][2] = c[j4][3] = 0.f;
                mma_bf16(c[j4], a0, Bf[jh * 4 + j4][0]);
                mma_bf16(c[j4], a1, Bf[jh * 4 + j4][1]);
            }
            #pragma unroll
            for (int j4 = 0; j4 < 4; j4++) {
                int j = jh * 4 + j4;
                int h0 = hw0 + j * 8 + 2 * tig;
                float2 e0 = *reinterpret_cast<const float2*>(e_row0 + h0);
                float2 e1 = *reinterpret_cast<const float2*>(e_row1 + h0);
                sum0 += ws2[j].x * tanh_ap(c[j4][0] + e0.x + gv2[j].x)
                      + ws2[j].y * tanh_ap(c[j4][1] + e0.y + gv2[j].y);
                sum1 += ws2[j].x * tanh_ap(c[j4][2] + e1.x + gv2[j].x)
                      + ws2[j].y * tanh_ap(c[j4][3] + e1.y + gv2[j].y);
            }
        }
        // reduce over tig (4 lanes sharing a row)
        sum0 += __shfl_xor_sync(0xFFFFFFFFu, sum0, 1);
        sum0 += __shfl_xor_sync(0xFFFFFFFFu, sum0, 2);
        sum1 += __shfl_xor_sync(0xFFFFFFFFu, sum1, 1);
        sum1 += __shfl_xor_sync(0xFFFFFFFFu, sum1, 2);
        if (tig == 0) {
            part[m * 16 + gid][wid]     = sum0;
            part[m * 16 + gid + 8][wid] = sum1;
        }
    }
    __syncthreads();

    // finalize: one t per thread -> exp -> block sum
    const int t = t0 + tid;
    float s = part[tid][0] + part[tid][1] + part[tid][2] + part[tid][3] + bsp[0];
    float e = __expf(s + mask[(size_t)t * B_DIM + b]);
    g_exp[(size_t)t * B_DIM + b] = e;

    float v = e;
    v += __shfl_xor_sync(0xFFFFFFFFu, v, 16);
    v += __shfl_xor_sync(0xFFFFFFFFu, v, 8);
    v += __shfl_xor_sync(0xFFFFFFFFu, v, 4);
    v += __shfl_xor_sync(0xFFFFFFFFu, v, 2);
    v += __shfl_xor_sync(0xFFFFFFFFu, v, 1);
    if (lane == 0) red4[wid] = v;
    __syncthreads();
    if (tid == 0)
        g_part[(size_t)blockIdx.x * B_DIM + b] = red4[0] + red4[1] + red4[2] + red4[3];
}

// ============================================================================
// Kernel C: normalize  out[t,b] = g_exp[t,b] / sum_b
// ============================================================================
__global__ void __launch_bounds__(128) norm_kernel(float* __restrict__ out)
{
    __shared__ float inv_s;
    const int b = blockIdx.y;
    const int tid = threadIdx.x;

    if (tid < 32) {
        float v = g_part[(size_t)tid * B_DIM + b];
        v += __shfl_xor_sync(0xFFFFFFFFu, v, 16);
        v += __shfl_xor_sync(0xFFFFFFFFu, v, 8);
        v += __shfl_xor_sync(0xFFFFFFFFu, v, 4);
        v += __shfl_xor_sync(0xFFFFFFFFu, v, 2);
        v += __shfl_xor_sync(0xFFFFFFFFu, v, 1);
        if (tid == 0) inv_s = 1.0f / v;
    }
    __syncthreads();

    int t = blockIdx.x * 128 + tid;
    out[(size_t)t * B_DIM + b] = g_exp[(size_t)t * B_DIM + b] * inv_s;
}

// ============================================================================
extern "C" void kernel_launch(void* const* d_in, const int* in_sizes, int n_in,
                              void* d_out, int out_size)
{
    const float* enc  = (const float*)d_in[0];
    const float* mask = (const float*)d_in[1];
    const float* lm   = (const float*)d_in[2];
    const float* prev = (const float*)d_in[3];
    const float* Wk   = (const float*)d_in[4];
    const float* bk   = (const float*)d_in[5];
    const float* Wg   = (const float*)d_in[6];
    const float* bg   = (const float*)d_in[7];
    const float* Ws   = (const float*)d_in[8];
    const float* bs   = (const float*)d_in[9];
    float* out = (float*)d_out;

    // Wk (256 blocks) + Wg (8 blocks)
    gemm_kernel<<<(K_DIM * H_DIM) / G_ROWS + H_DIM / G_ROWS, 128>>>(Wk, bk, Wg, bg, lm);
    // tensor-core conv + tanh + score + exp + partial sums
    score_kernel<<<dim3(T_DIM / T_BLK, B_DIM), 128>>>(enc, prev, mask, Ws, bs);
    // normalize
    norm_kernel<<<dim3(T_DIM / 128, B_DIM), 128>>>(out);
}